// round 14
// baseline (speedup 1.0000x reference)
#include <cuda_runtime.h>
#include <cuda_bf16.h>
#include <cstdint>

// ---------------------------------------------------------------------------
// Problem dims (fixed by the dataset)
// ---------------------------------------------------------------------------
#define MTOK   32768          // 8*4096 tokens
#define KDIM   512
#define NDIM   2048
#define WELEMS (NDIM*KDIM)    // 1,048,576
#define EPSQ   1e-6f

// GEMM tiling (bf16): K-chunk of 64 elems = 128 B per row (swizzle atom)
#define TM 128
#define TN 128
#define KC 64
#define NKC (KDIM/KC)                       // 8 chunks per tile
#define A_STAGE_B (TM*KC*2)                 // 16384 B
#define B_STAGE_B (TN*KC*2)                 // 16384 B
#define STAGE_B   (A_STAGE_B + B_STAGE_B)   // 32768 B
#define NSTAGE 3
#define SMEM_BYTES (NSTAGE*STAGE_B)         // 98304 B

// ---------------------------------------------------------------------------
// Scratch (device globals; no runtime allocation allowed)
// ---------------------------------------------------------------------------
__device__ __align__(16) float          g_part[256];
__device__ __align__(16) float          g_f[MTOK];  // per-token maxabs/127
__device__ __align__(16) __nv_bfloat16  g_qw[WELEMS];
__device__ __align__(16) __nv_bfloat16  g_qx[(size_t)MTOK*KDIM];
__device__ float                        g_wfac;     // max(mean|w|,eps)

// ---------------------------------------------------------------------------
// Helpers
// ---------------------------------------------------------------------------
__device__ __forceinline__ uint32_t smem_u32(const void* p) {
    uint32_t a;
    asm("{ .reg .u64 t; cvta.to.shared.u64 t, %1; cvt.u32.u64 %0, t; }" : "=r"(a) : "l"(p));
    return a;
}
__device__ __forceinline__ void cp_async16(uint32_t dst, const void* src) {
    asm volatile("cp.async.cg.shared.global [%0], [%1], 16;" :: "r"(dst), "l"(src) : "memory");
}
__device__ __forceinline__ void cp_commit() {
    asm volatile("cp.async.commit_group;" ::: "memory");
}
template <int N>
__device__ __forceinline__ void cp_wait() {
    asm volatile("cp.async.wait_group %0;" :: "n"(N) : "memory");
}
__device__ __forceinline__ void ldmatrix_x4(uint32_t& r0, uint32_t& r1, uint32_t& r2,
                                            uint32_t& r3, uint32_t addr) {
    asm volatile("ldmatrix.sync.aligned.m8n8.x4.shared.b16 {%0,%1,%2,%3}, [%4];"
                 : "=r"(r0), "=r"(r1), "=r"(r2), "=r"(r3) : "r"(addr));
}
__device__ __forceinline__ void hmma16816(float* c, const uint32_t* a, uint32_t b0, uint32_t b1) {
    asm volatile(
        "mma.sync.aligned.m16n8k16.row.col.f32.bf16.bf16.f32 "
        "{%0,%1,%2,%3}, {%4,%5,%6,%7}, {%8,%9}, {%0,%1,%2,%3};"
        : "+f"(c[0]), "+f"(c[1]), "+f"(c[2]), "+f"(c[3])
        : "r"(a[0]), "r"(a[1]), "r"(a[2]), "r"(a[3]), "r"(b0), "r"(b1));
}
__device__ __forceinline__ void stg_cs_v2(float* p, float a, float b) {
    asm volatile("st.global.cs.v2.f32 [%0], {%1, %2};" :: "l"(p), "f"(a), "f"(b) : "memory");
}
__device__ __forceinline__ uint32_t pk2(float a, float b) {
    return ((uint32_t)__bfloat16_as_ushort(__float2bfloat16(b)) << 16) |
           (uint32_t)__bfloat16_as_ushort(__float2bfloat16(a));
}

// ---------------------------------------------------------------------------
// 1) k_xq_ws: blocks [0,4096) = per-token x absmax-quant;
//             blocks [4096,4352) = |w| partial sums (overlapped, independent)
// ---------------------------------------------------------------------------
__global__ void k_xq_ws(const float* __restrict__ x, const float* __restrict__ w) {
    if (blockIdx.x < 4096) {
        int t = blockIdx.x * 8 + (threadIdx.x >> 5);
        int lid = threadIdx.x & 31;
        const float4* xr = reinterpret_cast<const float4*>(x + (size_t)t * KDIM) + lid * 4;
        float4 v[4];
        float amax = 0.f;
#pragma unroll
        for (int j = 0; j < 4; j++) {
            v[j] = xr[j];
            amax = fmaxf(amax, fmaxf(fmaxf(fabsf(v[j].x), fabsf(v[j].y)),
                                     fmaxf(fabsf(v[j].z), fabsf(v[j].w))));
        }
#pragma unroll
        for (int o = 16; o; o >>= 1) amax = fmaxf(amax, __shfl_xor_sync(0xffffffffu, amax, o));
        float m = fmaxf(amax, EPSQ);
        float s = 127.f / m;
        if (lid == 0) g_f[t] = m * (1.0f / 127.0f);
        uint4 u[2];
        uint32_t* up = &u[0].x;
#pragma unroll
        for (int j = 0; j < 4; j++) {
            up[j * 2 + 0] = pk2(fminf(fmaxf(rintf(v[j].x * s), -128.f), 127.f),
                                fminf(fmaxf(rintf(v[j].y * s), -128.f), 127.f));
            up[j * 2 + 1] = pk2(fminf(fmaxf(rintf(v[j].z * s), -128.f), 127.f),
                                fminf(fmaxf(rintf(v[j].w * s), -128.f), 127.f));
        }
        uint4* qr = reinterpret_cast<uint4*>(g_qx + (size_t)t * KDIM);
        qr[lid * 2 + 0] = u[0];
        qr[lid * 2 + 1] = u[1];
    } else {
        __shared__ float sred[8];
        int blk = blockIdx.x - 4096;                   // 0..255
        float s = 0.f;
        for (int i = blk * 256 + threadIdx.x; i < WELEMS; i += 256 * 256)
            s += fabsf(w[i]);
#pragma unroll
        for (int o = 16; o; o >>= 1) s += __shfl_xor_sync(0xffffffffu, s, o);
        if ((threadIdx.x & 31) == 0) sred[threadIdx.x >> 5] = s;
        __syncthreads();
        if (threadIdx.x < 32) {
            float v = (threadIdx.x < 8) ? sred[threadIdx.x] : 0.f;
#pragma unroll
            for (int o = 4; o; o >>= 1) v += __shfl_xor_sync(0xffffffffu, v, o);
            if (threadIdx.x == 0) g_part[blk] = v;
        }
    }
}

// ---------------------------------------------------------------------------
// 2) k_wq: every block re-reduces the 256 partials in an identical fixed
//    order (deterministic), then quantizes its slice of w to bf16 {-1,0,1}.
// ---------------------------------------------------------------------------
__global__ void k_wq(const float* __restrict__ w) {
    __shared__ float swscale;
    if (threadIdx.x < 32) {
        float v = 0.f;
#pragma unroll
        for (int j = 0; j < 8; j++) v += g_part[threadIdx.x * 8 + j];
#pragma unroll
        for (int o = 16; o; o >>= 1) v += __shfl_xor_sync(0xffffffffu, v, o);
        if (threadIdx.x == 0) {
            float m = fmaxf(v * (1.0f / (float)WELEMS), EPSQ);
            swscale = 1.0f / m;
            if (blockIdx.x == 0) g_wfac = m;
        }
    }
    __syncthreads();
    const float sc = swscale;

    int i = blockIdx.x * 256 + threadIdx.x;            // 16 weights per thread
    const float4* wr = reinterpret_cast<const float4*>(w) + i * 4;
    uint4 u[2];
    uint32_t* up = &u[0].x;
#pragma unroll
    for (int j = 0; j < 4; j++) {
        float4 v = wr[j];
        up[j * 2 + 0] = pk2(fminf(fmaxf(rintf(v.x * sc), -1.f), 1.f),
                            fminf(fmaxf(rintf(v.y * sc), -1.f), 1.f));
        up[j * 2 + 1] = pk2(fminf(fmaxf(rintf(v.z * sc), -1.f), 1.f),
                            fminf(fmaxf(rintf(v.w * sc), -1.f), 1.f));
    }
    reinterpret_cast<uint4*>(g_qw)[i * 2 + 0] = u[0];
    reinterpret_cast<uint4*>(g_qw)[i * 2 + 1] = u[1];
}

// ---------------------------------------------------------------------------
// 3) bf16 HMMA GEMM: 128x128 CTA tile, NOW 8 warps (2x4 grid of 64x32 warp
//    tiles), 256 threads, 2 CTAs/SM -> 16 warps/SM (4 per scheduler) to fill
//    the tensor-pipe gaps that 2-warp SMSPs expose. Same 3-stage cp.async
//    ring, one barrier per K-chunk, streaming stores.
// ---------------------------------------------------------------------------
__global__ void __launch_bounds__(256, 2)
k_gemm(const float* __restrict__ bias, float* __restrict__ out) {
    extern __shared__ char smem[];
    const uint32_t sb = smem_u32(smem);
    const int tid = threadIdx.x;
    const int wid = tid >> 5, lane = tid & 31;
    const int wm = wid >> 2, wn = wid & 3;          // 2 x 4 warp grid, 64x32 tiles
    const int ntile = blockIdx.x, mtile = blockIdx.y;
    const int m0 = mtile * TM, n0 = ntile * TN;

    const int arow = lane & 15;                     // A ldmatrix map
    const int achk = lane >> 4;
    const int brow = ((lane >> 4) << 3) + (lane & 7);   // B ldmatrix map
    const int bchk = (lane >> 3) & 1;

    float acc[4][4][4];                             // 4 m-frags x 4 n-frags
#pragma unroll
    for (int i = 0; i < 4; i++)
#pragma unroll
        for (int j = 0; j < 4; j++)
#pragma unroll
            for (int r = 0; r < 4; r++) acc[i][j][r] = 0.f;

    // --- cp.async tile loader: k-chunk c into stage s (256 threads) ---
    auto load_stage = [&](int c, int s) {
        const uint32_t sa = sb + s * STAGE_B;
#pragma unroll
        for (int i = 0; i < 4; i++) {
            int idx = tid + 256 * i;                // 0..1023
            int r = idx >> 3, ch = idx & 7;         // row, 16B segment
            uint32_t so = (uint32_t)(r * 128 + ((ch ^ (r & 7)) << 4));
            cp_async16(sa + so,             g_qx + ((size_t)(m0 + r) * KDIM + c * KC + ch * 8));
            cp_async16(sa + A_STAGE_B + so, g_qw + ((size_t)(n0 + r) * KDIM + c * KC + ch * 8));
        }
        cp_commit();
    };

    load_stage(0, 0);
    load_stage(1, 1);

#pragma unroll
    for (int c = 0; c < NKC; c++) {
        if (c < NKC - 1) cp_wait<1>(); else cp_wait<0>();
        __syncthreads();                            // chunk c visible; stage (c+2)%3 free
        if (c + 2 < NKC) load_stage(c + 2, (c + 2) % NSTAGE);

        const uint32_t sa = sb + (c % NSTAGE) * STAGE_B;
#pragma unroll
        for (int s = 0; s < 4; s++) {               // 4 x k16 per 64-chunk
            const int ch = 2 * s;
            uint32_t a[4][4], b[2][4];
#pragma unroll
            for (int mf = 0; mf < 4; mf++) {
                int row = wm * 64 + mf * 16 + arow;
                uint32_t ad = sa + (uint32_t)(row * 128 + (((ch + achk) ^ (row & 7)) << 4));
                ldmatrix_x4(a[mf][0], a[mf][1], a[mf][2], a[mf][3], ad);
            }
#pragma unroll
            for (int p = 0; p < 2; p++) {
                int nrow = wn * 32 + p * 16 + brow;
                uint32_t bd = sa + A_STAGE_B +
                              (uint32_t)(nrow * 128 + (((ch + bchk) ^ (nrow & 7)) << 4));
                ldmatrix_x4(b[p][0], b[p][1], b[p][2], b[p][3], bd);
            }
#pragma unroll
            for (int mf = 0; mf < 4; mf++) {
                hmma16816(acc[mf][0], a[mf], b[0][0], b[0][1]);
                hmma16816(acc[mf][1], a[mf], b[0][2], b[0][3]);
                hmma16816(acc[mf][2], a[mf], b[1][0], b[1][1]);
                hmma16816(acc[mf][3], a[mf], b[1][2], b[1][3]);
            }
        }
    }

    // --- epilogue: y = acc * (g_f[row] * wfac) + bias[col]; streaming stores ---
    const float wfac = g_wfac;
    const int t4 = lane >> 2, t2 = lane & 3;
#pragma unroll
    for (int mf = 0; mf < 4; mf++) {
        int gr0 = m0 + wm * 64 + mf * 16 + t4;
        float fa0 = g_f[gr0] * wfac;
        float fa1 = g_f[gr0 + 8] * wfac;
#pragma unroll
        for (int nf = 0; nf < 4; nf++) {
            int gc = n0 + wn * 32 + nf * 8 + t2 * 2;
            float b0 = bias[gc], b1 = bias[gc + 1];
            stg_cs_v2(out + (size_t)gr0 * NDIM + gc,
                      acc[mf][nf][0] * fa0 + b0, acc[mf][nf][1] * fa0 + b1);
            stg_cs_v2(out + (size_t)(gr0 + 8) * NDIM + gc,
                      acc[mf][nf][2] * fa1 + b0, acc[mf][nf][3] * fa1 + b1);
        }
    }
}

// ---------------------------------------------------------------------------
extern "C" void kernel_launch(void* const* d_in, const int* in_sizes, int n_in,
                              void* d_out, int out_size) {
    const float* x    = (const float*)d_in[0];
    const float* w    = (const float*)d_in[1];
    const float* bias = (const float*)d_in[2];
    float* out        = (float*)d_out;
    (void)in_sizes; (void)n_in; (void)out_size;

    cudaFuncSetAttribute(k_gemm, cudaFuncAttributeMaxDynamicSharedMemorySize, SMEM_BYTES);

    k_xq_ws<<<4096 + 256, 256>>>(x, w);        // launch 0: x-quant + |w| partials
    k_wq<<<256, 256>>>(w);                     // launch 1: finalize + w-quant
    k_gemm<<<dim3(NDIM / TN, MTOK / TM), 256, SMEM_BYTES>>>(bias, out);  // launch 2
}

// round 15
// speedup vs baseline: 1.0587x; 1.0587x over previous
#include <cuda_runtime.h>
#include <cuda_bf16.h>
#include <cstdint>

// ---------------------------------------------------------------------------
// Problem dims (fixed by the dataset)
// ---------------------------------------------------------------------------
#define MTOK   32768          // 8*4096 tokens
#define KDIM   512
#define NDIM   2048
#define WELEMS (NDIM*KDIM)    // 1,048,576
#define EPSQ   1e-6f

// GEMM tiling (bf16): K-chunk of 64 elems = 128 B per row (swizzle atom)
#define TM 128
#define TN 128
#define KC 64
#define NKC (KDIM/KC)                       // 8 chunks per tile
#define A_STAGE_B (TM*KC*2)                 // 16384 B
#define B_STAGE_B (TN*KC*2)                 // 16384 B
#define STAGE_B   (A_STAGE_B + B_STAGE_B)   // 32768 B
#define NSTAGE 3
#define SMEM_BYTES (NSTAGE*STAGE_B)         // 98304 B

// ---------------------------------------------------------------------------
// Scratch (device globals; no runtime allocation allowed)
// ---------------------------------------------------------------------------
__device__ __align__(16) float          g_part[256];
__device__ __align__(16) float          g_f[MTOK];  // per-token maxabs/127
__device__ __align__(16) __nv_bfloat16  g_qw[WELEMS];
__device__ __align__(16) __nv_bfloat16  g_qx[(size_t)MTOK*KDIM];
__device__ float                        g_wfac;     // max(mean|w|,eps)

// ---------------------------------------------------------------------------
// Helpers
// ---------------------------------------------------------------------------
__device__ __forceinline__ uint32_t smem_u32(const void* p) {
    uint32_t a;
    asm("{ .reg .u64 t; cvta.to.shared.u64 t, %1; cvt.u32.u64 %0, t; }" : "=r"(a) : "l"(p));
    return a;
}
__device__ __forceinline__ void cp_async16(uint32_t dst, const void* src) {
    asm volatile("cp.async.cg.shared.global [%0], [%1], 16;" :: "r"(dst), "l"(src) : "memory");
}
__device__ __forceinline__ void cp_commit() {
    asm volatile("cp.async.commit_group;" ::: "memory");
}
template <int N>
__device__ __forceinline__ void cp_wait() {
    asm volatile("cp.async.wait_group %0;" :: "n"(N) : "memory");
}
__device__ __forceinline__ void ldmatrix_x4(uint32_t& r0, uint32_t& r1, uint32_t& r2,
                                            uint32_t& r3, uint32_t addr) {
    asm volatile("ldmatrix.sync.aligned.m8n8.x4.shared.b16 {%0,%1,%2,%3}, [%4];"
                 : "=r"(r0), "=r"(r1), "=r"(r2), "=r"(r3) : "r"(addr));
}
__device__ __forceinline__ void hmma16816(float* c, const uint32_t* a, uint32_t b0, uint32_t b1) {
    asm volatile(
        "mma.sync.aligned.m16n8k16.row.col.f32.bf16.bf16.f32 "
        "{%0,%1,%2,%3}, {%4,%5,%6,%7}, {%8,%9}, {%0,%1,%2,%3};"
        : "+f"(c[0]), "+f"(c[1]), "+f"(c[2]), "+f"(c[3])
        : "r"(a[0]), "r"(a[1]), "r"(a[2]), "r"(a[3]), "r"(b0), "r"(b1));
}
__device__ __forceinline__ void stg_cs_v2(float* p, float a, float b) {
    asm volatile("st.global.cs.v2.f32 [%0], {%1, %2};" :: "l"(p), "f"(a), "f"(b) : "memory");
}
__device__ __forceinline__ uint32_t pk2(float a, float b) {
    return ((uint32_t)__bfloat16_as_ushort(__float2bfloat16(b)) << 16) |
           (uint32_t)__bfloat16_as_ushort(__float2bfloat16(a));
}

// ---------------------------------------------------------------------------
// 1) k_xq_ws: blocks [0,2048) = per-token x absmax-quant, 2 tokens per warp
//    (8 independent float4 loads in flight -> hides DRAM latency);
//    blocks [2048,2304) = |w| partial sums (overlapped, independent)
// ---------------------------------------------------------------------------
__global__ void k_xq_ws(const float* __restrict__ x, const float* __restrict__ w) {
    if (blockIdx.x < 2048) {
        int t0 = blockIdx.x * 16 + (threadIdx.x >> 5) * 2;   // 2 tokens per warp
        int lid = threadIdx.x & 31;
        float4 v[2][4];
        float amax[2] = {0.f, 0.f};
#pragma unroll
        for (int tk = 0; tk < 2; tk++) {
            const float4* xr =
                reinterpret_cast<const float4*>(x + (size_t)(t0 + tk) * KDIM) + lid * 4;
#pragma unroll
            for (int j = 0; j < 4; j++) {
                v[tk][j] = __ldcs(xr + j);               // read-once: evict-first
                amax[tk] = fmaxf(amax[tk],
                                 fmaxf(fmaxf(fabsf(v[tk][j].x), fabsf(v[tk][j].y)),
                                       fmaxf(fabsf(v[tk][j].z), fabsf(v[tk][j].w))));
            }
        }
#pragma unroll
        for (int tk = 0; tk < 2; tk++) {
#pragma unroll
            for (int o = 16; o; o >>= 1)
                amax[tk] = fmaxf(amax[tk], __shfl_xor_sync(0xffffffffu, amax[tk], o));
            float m = fmaxf(amax[tk], EPSQ);
            float s = 127.f / m;
            if (lid == 0) g_f[t0 + tk] = m * (1.0f / 127.0f);
            uint4 u[2];
            uint32_t* up = &u[0].x;
#pragma unroll
            for (int j = 0; j < 4; j++) {
                up[j * 2 + 0] = pk2(fminf(fmaxf(rintf(v[tk][j].x * s), -128.f), 127.f),
                                    fminf(fmaxf(rintf(v[tk][j].y * s), -128.f), 127.f));
                up[j * 2 + 1] = pk2(fminf(fmaxf(rintf(v[tk][j].z * s), -128.f), 127.f),
                                    fminf(fmaxf(rintf(v[tk][j].w * s), -128.f), 127.f));
            }
            uint4* qr = reinterpret_cast<uint4*>(g_qx + (size_t)(t0 + tk) * KDIM);
            qr[lid * 2 + 0] = u[0];
            qr[lid * 2 + 1] = u[1];
        }
    } else {
        __shared__ float sred[8];
        int blk = blockIdx.x - 2048;                   // 0..255
        float s = 0.f;
        for (int i = blk * 256 + threadIdx.x; i < WELEMS; i += 256 * 256)
            s += fabsf(w[i]);
#pragma unroll
        for (int o = 16; o; o >>= 1) s += __shfl_xor_sync(0xffffffffu, s, o);
        if ((threadIdx.x & 31) == 0) sred[threadIdx.x >> 5] = s;
        __syncthreads();
        if (threadIdx.x < 32) {
            float v = (threadIdx.x < 8) ? sred[threadIdx.x] : 0.f;
#pragma unroll
            for (int o = 4; o; o >>= 1) v += __shfl_xor_sync(0xffffffffu, v, o);
            if (threadIdx.x == 0) g_part[blk] = v;
        }
    }
}

// ---------------------------------------------------------------------------
// 2) k_wq: every block re-reduces the 256 partials in an identical fixed
//    order (deterministic), then quantizes its slice of w to bf16 {-1,0,1}.
// ---------------------------------------------------------------------------
__global__ void k_wq(const float* __restrict__ w) {
    __shared__ float swscale;
    if (threadIdx.x < 32) {
        float v = 0.f;
#pragma unroll
        for (int j = 0; j < 8; j++) v += g_part[threadIdx.x * 8 + j];
#pragma unroll
        for (int o = 16; o; o >>= 1) v += __shfl_xor_sync(0xffffffffu, v, o);
        if (threadIdx.x == 0) {
            float m = fmaxf(v * (1.0f / (float)WELEMS), EPSQ);
            swscale = 1.0f / m;
            if (blockIdx.x == 0) g_wfac = m;
        }
    }
    __syncthreads();
    const float sc = swscale;

    int i = blockIdx.x * 256 + threadIdx.x;            // 16 weights per thread
    const float4* wr = reinterpret_cast<const float4*>(w) + i * 4;
    uint4 u[2];
    uint32_t* up = &u[0].x;
#pragma unroll
    for (int j = 0; j < 4; j++) {
        float4 v = wr[j];
        up[j * 2 + 0] = pk2(fminf(fmaxf(rintf(v.x * sc), -1.f), 1.f),
                            fminf(fmaxf(rintf(v.y * sc), -1.f), 1.f));
        up[j * 2 + 1] = pk2(fminf(fmaxf(rintf(v.z * sc), -1.f), 1.f),
                            fminf(fmaxf(rintf(v.w * sc), -1.f), 1.f));
    }
    reinterpret_cast<uint4*>(g_qw)[i * 2 + 0] = u[0];
    reinterpret_cast<uint4*>(g_qw)[i * 2 + 1] = u[1];
}

// ---------------------------------------------------------------------------
// 3) bf16 HMMA GEMM (R13 body, empirical optimum — DO NOT PERTURB):
//    128x128 CTA tile, 4 warps (2x2, 64x64), 3-stage cp.async ring,
//    one barrier per K-chunk, streaming stores.
// ---------------------------------------------------------------------------
__global__ void __launch_bounds__(128, 2)
k_gemm(const float* __restrict__ bias, float* __restrict__ out) {
    extern __shared__ char smem[];
    const uint32_t sb = smem_u32(smem);
    const int tid = threadIdx.x;
    const int wid = tid >> 5, lane = tid & 31;
    const int wm = wid >> 1, wn = wid & 1;          // 2 x 2 warp grid, 64x64 tiles
    const int ntile = blockIdx.x, mtile = blockIdx.y;
    const int m0 = mtile * TM, n0 = ntile * TN;

    const int arow = lane & 15;                     // A ldmatrix map
    const int achk = lane >> 4;
    const int brow = ((lane >> 4) << 3) + (lane & 7);   // B ldmatrix map
    const int bchk = (lane >> 3) & 1;

    float acc[4][8][4];                             // 4 m-frags x 8 n-frags
#pragma unroll
    for (int i = 0; i < 4; i++)
#pragma unroll
        for (int j = 0; j < 8; j++)
#pragma unroll
            for (int r = 0; r < 4; r++) acc[i][j][r] = 0.f;

    // --- cp.async tile loader: k-chunk c into stage s (128 threads) ---
    auto load_stage = [&](int c, int s) {
        const uint32_t sa = sb + s * STAGE_B;
#pragma unroll
        for (int i = 0; i < 8; i++) {
            int idx = tid + 128 * i;                // 0..1023
            int r = idx >> 3, ch = idx & 7;         // row, 16B segment
            uint32_t so = (uint32_t)(r * 128 + ((ch ^ (r & 7)) << 4));
            cp_async16(sa + so,             g_qx + ((size_t)(m0 + r) * KDIM + c * KC + ch * 8));
            cp_async16(sa + A_STAGE_B + so, g_qw + ((size_t)(n0 + r) * KDIM + c * KC + ch * 8));
        }
        cp_commit();
    };

    load_stage(0, 0);
    load_stage(1, 1);

#pragma unroll
    for (int c = 0; c < NKC; c++) {
        if (c < NKC - 1) cp_wait<1>(); else cp_wait<0>();
        __syncthreads();                            // chunk c visible; stage (c+2)%3 free
        if (c + 2 < NKC) load_stage(c + 2, (c + 2) % NSTAGE);

        const uint32_t sa = sb + (c % NSTAGE) * STAGE_B;
#pragma unroll
        for (int s = 0; s < 4; s++) {               // 4 x k16 per 64-chunk
            const int ch = 2 * s;
            uint32_t a[4][4], b[4][4];
#pragma unroll
            for (int mf = 0; mf < 4; mf++) {
                int row = wm * 64 + mf * 16 + arow;
                uint32_t ad = sa + (uint32_t)(row * 128 + (((ch + achk) ^ (row & 7)) << 4));
                ldmatrix_x4(a[mf][0], a[mf][1], a[mf][2], a[mf][3], ad);
            }
            {
                int nrow = wn * 64 + 0 * 16 + brow;
                uint32_t bd = sa + A_STAGE_B +
                              (uint32_t)(nrow * 128 + (((ch + bchk) ^ (nrow & 7)) << 4));
                ldmatrix_x4(b[0][0], b[0][1], b[0][2], b[0][3], bd);
            }
            {
                int nrow = wn * 64 + 1 * 16 + brow;
                uint32_t bd = sa + A_STAGE_B +
                              (uint32_t)(nrow * 128 + (((ch + bchk) ^ (nrow & 7)) << 4));
                ldmatrix_x4(b[1][0], b[1][1], b[1][2], b[1][3], bd);
            }
#pragma unroll
            for (int mf = 0; mf < 4; mf++) {
                hmma16816(acc[mf][0], a[mf], b[0][0], b[0][1]);
                hmma16816(acc[mf][1], a[mf], b[0][2], b[0][3]);
            }
            {
                int nrow = wn * 64 + 2 * 16 + brow;
                uint32_t bd = sa + A_STAGE_B +
                              (uint32_t)(nrow * 128 + (((ch + bchk) ^ (nrow & 7)) << 4));
                ldmatrix_x4(b[2][0], b[2][1], b[2][2], b[2][3], bd);
            }
#pragma unroll
            for (int mf = 0; mf < 4; mf++) {
                hmma16816(acc[mf][2], a[mf], b[1][0], b[1][1]);
                hmma16816(acc[mf][3], a[mf], b[1][2], b[1][3]);
            }
            {
                int nrow = wn * 64 + 3 * 16 + brow;
                uint32_t bd = sa + A_STAGE_B +
                              (uint32_t)(nrow * 128 + (((ch + bchk) ^ (nrow & 7)) << 4));
                ldmatrix_x4(b[3][0], b[3][1], b[3][2], b[3][3], bd);
            }
#pragma unroll
            for (int mf = 0; mf < 4; mf++) {
                hmma16816(acc[mf][4], a[mf], b[2][0], b[2][1]);
                hmma16816(acc[mf][5], a[mf], b[2][2], b[2][3]);
            }
#pragma unroll
            for (int mf = 0; mf < 4; mf++) {
                hmma16816(acc[mf][6], a[mf], b[3][0], b[3][1]);
                hmma16816(acc[mf][7], a[mf], b[3][2], b[3][3]);
            }
        }
    }

    // --- epilogue: y = acc * (g_f[row] * wfac) + bias[col]; streaming stores ---
    const float wfac = g_wfac;
    const int t4 = lane >> 2, t2 = lane & 3;
#pragma unroll
    for (int mf = 0; mf < 4; mf++) {
        int gr0 = m0 + wm * 64 + mf * 16 + t4;
        float fa0 = g_f[gr0] * wfac;
        float fa1 = g_f[gr0 + 8] * wfac;
#pragma unroll
        for (int nf = 0; nf < 8; nf++) {
            int gc = n0 + wn * 64 + nf * 8 + t2 * 2;
            float b0 = bias[gc], b1 = bias[gc + 1];
            stg_cs_v2(out + (size_t)gr0 * NDIM + gc,
                      acc[mf][nf][0] * fa0 + b0, acc[mf][nf][1] * fa0 + b1);
            stg_cs_v2(out + (size_t)(gr0 + 8) * NDIM + gc,
                      acc[mf][nf][2] * fa1 + b0, acc[mf][nf][3] * fa1 + b1);
        }
    }
}

// ---------------------------------------------------------------------------
extern "C" void kernel_launch(void* const* d_in, const int* in_sizes, int n_in,
                              void* d_out, int out_size) {
    const float* x    = (const float*)d_in[0];
    const float* w    = (const float*)d_in[1];
    const float* bias = (const float*)d_in[2];
    float* out        = (float*)d_out;
    (void)in_sizes; (void)n_in; (void)out_size;

    cudaFuncSetAttribute(k_gemm, cudaFuncAttributeMaxDynamicSharedMemorySize, SMEM_BYTES);

    k_xq_ws<<<2048 + 256, 256>>>(x, w);        // launch 0: x-quant (MLP 8) + |w| partials
    k_wq<<<256, 256>>>(w);                     // launch 1: finalize + w-quant
    k_gemm<<<dim3(NDIM / TN, MTOK / TM), 128, SMEM_BYTES>>>(bias, out);  // launch 2
}